// round 8
// baseline (speedup 1.0000x reference)
#include <cuda_runtime.h>

// ---------------------------------------------------------------------------
// Fused: channel-mix (64->16) -> double-unfold 3x3 along W (masked) ->
//        group conv mix (8g x 9taps -> 32) -> roll(+1,H) -> NCHW out.
//
// One CTA per batch image (grid=128, 512 threads, 128 regs).
// Stage 1: T4 transposed to smem, p-major rows of 20 floats (16B aligned).
// Stage 2: even/odd packed-accumulator split (A: even taps, B: odd taps);
//          E loaded via LDS.128; g=0 peeled with mul.rn.f32x2 (no acc zeroing);
//          g=1..7 fully unrolled for cross-iteration load scheduling.
//          Weights pre-dup-packed (w,w) ulls in smem. Rank-1 edge
//          corrections at w=0/w=13 fold onto E[1]/E[7].
// ---------------------------------------------------------------------------

typedef unsigned long long ull;

#define ROWP   20                     // floats per p-row (80B, 16B aligned)
#define ROWBLK (16*ROWP)              // 320 floats per (g,h) block
#define T4N    (8*14*ROWBLK)          // 35840 floats
#define WEFFD_N (8*5*32)              // dup-packed weights (ull)
#define WMIXN  1024                   // 64*16 floats
#define CORRN  (8*32)                 // ulls per correction table
#define SMEM_BYTES (T4N*4 + WEFFD_N*8 + WMIXN*4 + CORRN*8*2)   // 161792

__device__ __forceinline__ ull pack2(float lo, float hi){
    ull r; asm("mov.b64 %0, {%1, %2};" : "=l"(r) : "f"(lo), "f"(hi)); return r;
}
__device__ __forceinline__ void unpack2(ull v, float &lo, float &hi){
    asm("mov.b64 {%0, %1}, %2;" : "=f"(lo), "=f"(hi) : "l"(v));
}
__device__ __forceinline__ void ffma2(ull &d, ull a, ull b){
    asm("fma.rn.f32x2 %0, %1, %2, %0;" : "+l"(d) : "l"(a), "l"(b));
}
__device__ __forceinline__ void fmul2(ull &d, ull a, ull b){
    asm("mul.rn.f32x2 %0, %1, %2;" : "=l"(d) : "l"(a), "l"(b));
}

__global__ void __launch_bounds__(512, 1)
fused_mix_unfold_conv(const float* __restrict__ x,
                      const float* __restrict__ wconv,
                      const float* __restrict__ wmix,
                      float* __restrict__ out)
{
    extern __shared__ float smem[];
    float* t4s     = smem;                       // [g][h] blocks of ROWBLK
    ull*   weffd   = (ull*)(smem + T4N);         // [g][d][j] packed (w,w)
    float* wmixs   = (float*)(weffd + WEFFD_N);  // [j64][p16]
    ull*   corr0d  = (ull*)(wmixs + WMIXN);      // [g][j]  (-c0, 0)
    ull*   corr13d = corr0d + CORRN;             // [g][j]  (0, -c13)

    const int tid = threadIdx.x;
    const int b   = blockIdx.x;

    // ---------------- prologue --------------------------------------------
    for (int i = tid; i < WMIXN; i += 512) wmixs[i] = wmix[i];

    // zero pad wd slots {0,1,16,17} for all (g,h,p)
    for (int i = tid; i < 8*14*16*4; i += 512) {
        int blk = i >> 6, r = i & 63;
        int p = r >> 2, wi = r & 3;
        int wd = (wi < 2) ? wi : (wi + 14);
        t4s[blk*ROWBLK + p*ROWP + wd] = 0.f;
    }

    // interior dup-packed Weff[g][d][j] = (a,a), a = sum_kb wconv[g][kb][d-kb][j]
    for (int e = tid; e < WEFFD_N; e += 512) {
        int j = e & 31;
        int d = (e >> 5) % 5;
        int g = e / 160;
        float a = 0.f;
        #pragma unroll
        for (int kb = 0; kb < 3; ++kb) {
            int ka = d - kb;
            if (ka >= 0 && ka <= 2)
                a += wconv[((g*3 + kb)*3 + ka)*32 + j];
        }
        weffd[e] = pack2(a, a);
    }

    // corrections: w=0 loses kb=0 tap (d=2): c0 = wconv[g][0][2][j], hits t[0]=lo(E[1])
    //              w=13 loses kb=2 tap (d=2): c13 = wconv[g][2][0][j], hits t[13]=hi(E[7])
    for (int e = tid; e < CORRN; e += 512) {
        int j = e & 31, g = e >> 5;
        corr0d [e] = pack2(-wconv[((g*3 + 0)*3 + 2)*32 + j], 0.f);
        corr13d[e] = pack2(0.f, -wconv[((g*3 + 2)*3 + 0)*32 + j]);
    }
    __syncthreads();

    // ---------------- stage 1: T4[g,h,w,p] = sum_j x[b,j,s] * wmix[j,p] ----
    if (tid < 392) {
        const float* xb = x + (size_t)b * 100352 + tid * 4;
        ull acc[4][8];
        #pragma unroll
        for (int pt = 0; pt < 4; ++pt)
            #pragma unroll
            for (int pp = 0; pp < 8; ++pp) acc[pt][pp] = 0ull;

        #pragma unroll 8
        for (int j = 0; j < 64; ++j) {
            float4 xv = *(const float4*)(xb + j * 1568);
            const ulonglong2* wrow = (const ulonglong2*)(wmixs + j * 16);
            ulonglong2 w01 = wrow[0], w23 = wrow[1], w45 = wrow[2], w67 = wrow[3];
            ull wp[8] = {w01.x, w01.y, w23.x, w23.y, w45.x, w45.y, w67.x, w67.y};
            ull xbc[4] = {pack2(xv.x, xv.x), pack2(xv.y, xv.y),
                          pack2(xv.z, xv.z), pack2(xv.w, xv.w)};
            #pragma unroll
            for (int pt = 0; pt < 4; ++pt)
                #pragma unroll
                for (int pp = 0; pp < 8; ++pp)
                    ffma2(acc[pt][pp], xbc[pt], wp[pp]);
        }
        #pragma unroll
        for (int pt = 0; pt < 4; ++pt) {
            int s = tid * 4 + pt;
            int g = s / 196, rem = s % 196;
            int h = rem / 14, w = rem % 14;
            float* dst = t4s + (g*14 + h)*ROWBLK + (w + 2);
            float v[16];
            #pragma unroll
            for (int q = 0; q < 8; ++q) unpack2(acc[pt][q], v[2*q], v[2*q+1]);
            #pragma unroll
            for (int p = 0; p < 16; ++p) dst[p*ROWP] = v[p];
        }
    }
    __syncthreads();

    // ---------------- stage 2 ---------------------------------------------
    const int lid = tid & 31;
    const int wid = tid >> 5;
    const int p   = lid & 15;
    const int jg  = lid >> 4;               // 0..1

    const size_t obase = (size_t)b * 100352;

    #pragma unroll 1
    for (int it = 0; it < 7; ++it) {
        int task = wid + 16*it;             // 112 tasks, 7/warp, SMSP-balanced
        int jq = task & 7;
        int h  = task >> 3;
        int jb = jq*4 + jg*2;               // this thread's 2 j's: jb, jb+1

        // A[i] = (out[2i], out[2i+1]) : even taps d=0,2,4 + corrections
        // B[i] = (out[2i-1], out[2i]) : odd taps d=1,3 (pads absorb edges)
        ull A0[7], A1[7], B0[8], B1[8];

        const float* t4h = t4s + h*ROWBLK + p*ROWP;   // + g*14*ROWBLK per g
        const ull*   wgb = weffd + jb;                 // + g*160 per g

        #define LOAD_E(G)                                                    \
            ull E[9];                                                        \
            {                                                                \
                const float4* r4 = (const float4*)(t4h + (G)*14*ROWBLK);     \
                float4 q0 = r4[0], q1 = r4[1], q2 = r4[2], q3 = r4[3];       \
                float2 q4 = *(const float2*)(t4h + (G)*14*ROWBLK + 16);      \
                E[0]=pack2(q0.x,q0.y); E[1]=pack2(q0.z,q0.w);                \
                E[2]=pack2(q1.x,q1.y); E[3]=pack2(q1.z,q1.w);                \
                E[4]=pack2(q2.x,q2.y); E[5]=pack2(q2.z,q2.w);                \
                E[6]=pack2(q3.x,q3.y); E[7]=pack2(q3.z,q3.w);                \
                E[8]=pack2(q4.x,q4.y);                                       \
            }

        #define LOAD_W(G)                                                    \
            const ull* wg = wgb + (G)*160;                                   \
            ulonglong2 w0 = *(const ulonglong2*)(wg);                        \
            ulonglong2 w1 = *(const ulonglong2*)(wg + 32);                   \
            ulonglong2 w2 = *(const ulonglong2*)(wg + 64);                   \
            ulonglong2 w3 = *(const ulonglong2*)(wg + 96);                   \
            ulonglong2 w4 = *(const ulonglong2*)(wg + 128);                  \
            ulonglong2 c0 = *(const ulonglong2*)(corr0d  + (G)*32 + jb);     \
            ulonglong2 c3 = *(const ulonglong2*)(corr13d + (G)*32 + jb);

        // ---- g = 0 peel: mul-init accumulators ----
        {
            LOAD_E(0)
            LOAD_W(0)
            #pragma unroll
            for (int i = 0; i < 7; ++i) {
                fmul2(A0[i], E[i],   w0.x);  fmul2(A1[i], E[i],   w0.y);
                ffma2(A0[i], E[i+1], w2.x);  ffma2(A1[i], E[i+1], w2.y);
                ffma2(A0[i], E[i+2], w4.x);  ffma2(A1[i], E[i+2], w4.y);
            }
            #pragma unroll
            for (int i = 0; i < 8; ++i) {
                fmul2(B0[i], E[i],   w1.x);  fmul2(B1[i], E[i],   w1.y);
                ffma2(B0[i], E[i+1], w3.x);  ffma2(B1[i], E[i+1], w3.y);
            }
            ffma2(A0[0], E[1], c0.x);  ffma2(A1[0], E[1], c0.y);
            ffma2(A0[6], E[7], c3.x);  ffma2(A1[6], E[7], c3.y);
        }

        // ---- g = 1..7 fully unrolled ----
        #pragma unroll
        for (int g = 1; g < 8; ++g) {
            LOAD_E(g)
            LOAD_W(g)
            #pragma unroll
            for (int i = 0; i < 7; ++i) {
                ffma2(A0[i], E[i],   w0.x);  ffma2(A1[i], E[i],   w0.y);
                ffma2(A0[i], E[i+1], w2.x);  ffma2(A1[i], E[i+1], w2.y);
                ffma2(A0[i], E[i+2], w4.x);  ffma2(A1[i], E[i+2], w4.y);
            }
            #pragma unroll
            for (int i = 0; i < 8; ++i) {
                ffma2(B0[i], E[i],   w1.x);  ffma2(B1[i], E[i],   w1.y);
                ffma2(B0[i], E[i+1], w3.x);  ffma2(B1[i], E[i+1], w3.y);
            }
            ffma2(A0[0], E[1], c0.x);  ffma2(A1[0], E[1], c0.y);
            ffma2(A0[6], E[7], c3.x);  ffma2(A1[6], E[7], c3.y);
        }
        #undef LOAD_E
        #undef LOAD_W

        int h_o = h + 1; if (h_o == 14) h_o = 0;   // roll(+1, H)

        #pragma unroll
        for (int jj = 0; jj < 2; ++jj) {
            ull* A = jj ? A1 : A0;
            ull* B = jj ? B1 : B0;
            float o[14];
            #pragma unroll
            for (int i = 0; i < 7; ++i) {
                float al, ah, bl0, bh0, bl1, bh1;
                unpack2(A[i],   al,  ah);
                unpack2(B[i],   bl0, bh0);
                unpack2(B[i+1], bl1, bh1);
                o[2*i]   = al + bh0;
                o[2*i+1] = ah + bl1;
            }
            int ch = (jb + jj)*16 + p;
            float* ob = out + obase + (size_t)ch*196 + h_o*14;
            if ((h_o & 1) == 0) {               // 16B aligned
                *(float4*)(ob)      = make_float4(o[0], o[1], o[2], o[3]);
                *(float4*)(ob + 4)  = make_float4(o[4], o[5], o[6], o[7]);
                *(float4*)(ob + 8)  = make_float4(o[8], o[9], o[10], o[11]);
                *(float2*)(ob + 12) = make_float2(o[12], o[13]);
            } else {                            // 8B aligned
                *(float2*)(ob)      = make_float2(o[0], o[1]);
                *(float4*)(ob + 2)  = make_float4(o[2], o[3], o[4], o[5]);
                *(float4*)(ob + 6)  = make_float4(o[6], o[7], o[8], o[9]);
                *(float4*)(ob + 10) = make_float4(o[10], o[11], o[12], o[13]);
            }
        }
    }
}

extern "C" void kernel_launch(void* const* d_in, const int* in_sizes, int n_in,
                              void* d_out, int out_size) {
    const float* x     = (const float*)d_in[0];
    const float* wconv = (const float*)d_in[1];
    const float* wmix  = (const float*)d_in[2];
    float* out = (float*)d_out;
    (void)in_sizes; (void)n_in; (void)out_size;

    cudaFuncSetAttribute(fused_mix_unfold_conv,
                         cudaFuncAttributeMaxDynamicSharedMemorySize,
                         SMEM_BYTES);
    fused_mix_unfold_conv<<<128, 512, SMEM_BYTES>>>(x, wconv, wmix, out);
}

// round 9
// speedup vs baseline: 3.1772x; 3.1772x over previous
#include <cuda_runtime.h>

// ---------------------------------------------------------------------------
// Fused: channel-mix (64->16) -> double-unfold 3x3 along W (masked) ->
//        group conv mix (8g x 9taps -> 32) -> roll(+1,H) -> NCHW out.
//
// One CTA per batch image (grid=128, 512 threads, 128 regs).
// Stage 1: T4 transposed to smem, p-major rows of 18 floats (bank-permuted:
//          (p*18) mod 32 is a perfect permutation -> conflict-free LDS.64).
// Stage 2: even/odd packed-accumulator split (A: even taps, B: odd taps),
//          E loaded as 9 conflict-free LDS.64 directly into ulls;
//          g=0 peeled with mul.rn.f32x2 (no accumulator zero-init);
//          g-loop unroll 1 (full unroll spills at the 128-reg clamp).
//          Weights pre-dup-packed (w,w) ulls in smem. Rank-1 edge
//          corrections at w=0/w=13 fold onto E[1]/E[7].
// ---------------------------------------------------------------------------

typedef unsigned long long ull;

#define ROWP   18                     // floats per p-row (72B, bank-permuted)
#define ROWBLK (16*ROWP + 2)          // 290 floats per (g,h) block (8B-align pad)
#define T4N    (8*14*ROWBLK)          // 32480 floats
#define WEFFD_N (8*5*32)              // dup-packed weights (ull)
#define WMIXN  1024                   // 64*16 floats
#define CORRN  (8*32)                 // ulls per correction table
#define SMEM_BYTES (T4N*4 + WEFFD_N*8 + WMIXN*4 + CORRN*8*2)   // 148352

__device__ __forceinline__ ull pack2(float lo, float hi){
    ull r; asm("mov.b64 %0, {%1, %2};" : "=l"(r) : "f"(lo), "f"(hi)); return r;
}
__device__ __forceinline__ void unpack2(ull v, float &lo, float &hi){
    asm("mov.b64 {%0, %1}, %2;" : "=f"(lo), "=f"(hi) : "l"(v));
}
__device__ __forceinline__ void ffma2(ull &d, ull a, ull b){
    asm("fma.rn.f32x2 %0, %1, %2, %0;" : "+l"(d) : "l"(a), "l"(b));
}
__device__ __forceinline__ void fmul2(ull &d, ull a, ull b){
    asm("mul.rn.f32x2 %0, %1, %2;" : "=l"(d) : "l"(a), "l"(b));
}

__global__ void __launch_bounds__(512, 1)
fused_mix_unfold_conv(const float* __restrict__ x,
                      const float* __restrict__ wconv,
                      const float* __restrict__ wmix,
                      float* __restrict__ out)
{
    extern __shared__ float smem[];
    float* t4s     = smem;                       // [g][h] blocks of ROWBLK
    ull*   weffd   = (ull*)(smem + T4N);         // [g][d][j] packed (w,w)
    float* wmixs   = (float*)(weffd + WEFFD_N);  // [j64][p16]
    ull*   corr0d  = (ull*)(wmixs + WMIXN);      // [g][j]  (-c0, 0)
    ull*   corr13d = corr0d + CORRN;             // [g][j]  (0, -c13)

    const int tid = threadIdx.x;
    const int b   = blockIdx.x;

    // ---------------- prologue --------------------------------------------
    for (int i = tid; i < WMIXN; i += 512) wmixs[i] = wmix[i];

    // zero pad wd slots {0,1,16,17} for all (g,h,p)
    for (int i = tid; i < 8*14*16*4; i += 512) {
        int blk = i >> 6, r = i & 63;
        int p = r >> 2, wi = r & 3;
        int wd = (wi < 2) ? wi : (wi + 14);
        t4s[blk*ROWBLK + p*ROWP + wd] = 0.f;
    }

    // interior dup-packed Weff[g][d][j] = (a,a), a = sum_kb wconv[g][kb][d-kb][j]
    for (int e = tid; e < WEFFD_N; e += 512) {
        int j = e & 31;
        int d = (e >> 5) % 5;
        int g = e / 160;
        float a = 0.f;
        #pragma unroll
        for (int kb = 0; kb < 3; ++kb) {
            int ka = d - kb;
            if (ka >= 0 && ka <= 2)
                a += wconv[((g*3 + kb)*3 + ka)*32 + j];
        }
        weffd[e] = pack2(a, a);
    }

    // corrections: w=0 loses kb=0 tap (d=2): c0 = wconv[g][0][2][j], hits t[0]=lo(E[1])
    //              w=13 loses kb=2 tap (d=2): c13 = wconv[g][2][0][j], hits t[13]=hi(E[7])
    for (int e = tid; e < CORRN; e += 512) {
        int j = e & 31, g = e >> 5;
        corr0d [e] = pack2(-wconv[((g*3 + 0)*3 + 2)*32 + j], 0.f);
        corr13d[e] = pack2(0.f, -wconv[((g*3 + 2)*3 + 0)*32 + j]);
    }
    __syncthreads();

    // ---------------- stage 1: T4[g,h,w,p] = sum_j x[b,j,s] * wmix[j,p] ----
    if (tid < 392) {
        const float* xb = x + (size_t)b * 100352 + tid * 4;
        ull acc[4][8];
        #pragma unroll
        for (int pt = 0; pt < 4; ++pt)
            #pragma unroll
            for (int pp = 0; pp < 8; ++pp) acc[pt][pp] = 0ull;

        #pragma unroll 8
        for (int j = 0; j < 64; ++j) {
            float4 xv = *(const float4*)(xb + j * 1568);
            const ulonglong2* wrow = (const ulonglong2*)(wmixs + j * 16);
            ulonglong2 w01 = wrow[0], w23 = wrow[1], w45 = wrow[2], w67 = wrow[3];
            ull wp[8] = {w01.x, w01.y, w23.x, w23.y, w45.x, w45.y, w67.x, w67.y};
            ull xbc[4] = {pack2(xv.x, xv.x), pack2(xv.y, xv.y),
                          pack2(xv.z, xv.z), pack2(xv.w, xv.w)};
            #pragma unroll
            for (int pt = 0; pt < 4; ++pt)
                #pragma unroll
                for (int pp = 0; pp < 8; ++pp)
                    ffma2(acc[pt][pp], xbc[pt], wp[pp]);
        }
        #pragma unroll
        for (int pt = 0; pt < 4; ++pt) {
            int s = tid * 4 + pt;
            int g = s / 196, rem = s % 196;
            int h = rem / 14, w = rem % 14;
            float* dst = t4s + (g*14 + h)*ROWBLK + (w + 2);
            float v[16];
            #pragma unroll
            for (int q = 0; q < 8; ++q) unpack2(acc[pt][q], v[2*q], v[2*q+1]);
            #pragma unroll
            for (int p = 0; p < 16; ++p) dst[p*ROWP] = v[p];
        }
    }
    __syncthreads();

    // ---------------- stage 2 ---------------------------------------------
    const int lid = tid & 31;
    const int wid = tid >> 5;
    const int p   = lid & 15;
    const int jg  = lid >> 4;               // 0..1

    const size_t obase = (size_t)b * 100352;

    #pragma unroll 1
    for (int it = 0; it < 7; ++it) {
        int task = wid + 16*it;             // 112 tasks, 7/warp, SMSP-balanced
        int jq = task & 7;
        int h  = task >> 3;
        int jb = jq*4 + jg*2;               // this thread's 2 j's: jb, jb+1

        // A[i] = (out[2i], out[2i+1]) : even taps d=0,2,4 + corrections
        // B[i] = (out[2i-1], out[2i]) : odd taps d=1,3 (pads absorb edges)
        ull A0[7], A1[7], B0[8], B1[8];

        const float* t4h = t4s + h*ROWBLK + p*ROWP;

        // ---- g = 0 peel: mul-init accumulators ----
        {
            const ull* row = (const ull*)t4h;
            ull E[9];
            #pragma unroll
            for (int k = 0; k < 9; ++k) E[k] = row[k];

            const ull* wg = weffd + jb;
            ulonglong2 w0 = *(const ulonglong2*)(wg);
            ulonglong2 w1 = *(const ulonglong2*)(wg + 32);
            ulonglong2 w2 = *(const ulonglong2*)(wg + 64);
            ulonglong2 w3 = *(const ulonglong2*)(wg + 96);
            ulonglong2 w4 = *(const ulonglong2*)(wg + 128);
            ulonglong2 c0 = *(const ulonglong2*)(corr0d  + jb);
            ulonglong2 c3 = *(const ulonglong2*)(corr13d + jb);

            #pragma unroll
            for (int i = 0; i < 7; ++i) {
                fmul2(A0[i], E[i],   w0.x);  fmul2(A1[i], E[i],   w0.y);
                ffma2(A0[i], E[i+1], w2.x);  ffma2(A1[i], E[i+1], w2.y);
                ffma2(A0[i], E[i+2], w4.x);  ffma2(A1[i], E[i+2], w4.y);
            }
            #pragma unroll
            for (int i = 0; i < 8; ++i) {
                fmul2(B0[i], E[i],   w1.x);  fmul2(B1[i], E[i],   w1.y);
                ffma2(B0[i], E[i+1], w3.x);  ffma2(B1[i], E[i+1], w3.y);
            }
            ffma2(A0[0], E[1], c0.x);  ffma2(A1[0], E[1], c0.y);
            ffma2(A0[6], E[7], c3.x);  ffma2(A1[6], E[7], c3.y);
        }

        // ---- g = 1..7 (unroll 1: keeps live set under the 128-reg clamp) --
        #pragma unroll 1
        for (int g = 1; g < 8; ++g) {
            const ull* row = (const ull*)(t4h + g*14*ROWBLK);
            ull E[9];
            #pragma unroll
            for (int k = 0; k < 9; ++k) E[k] = row[k];

            const ull* wg = weffd + g*160 + jb;
            ulonglong2 w0 = *(const ulonglong2*)(wg);
            ulonglong2 w1 = *(const ulonglong2*)(wg + 32);
            ulonglong2 w2 = *(const ulonglong2*)(wg + 64);
            ulonglong2 w3 = *(const ulonglong2*)(wg + 96);
            ulonglong2 w4 = *(const ulonglong2*)(wg + 128);
            ulonglong2 c0 = *(const ulonglong2*)(corr0d  + g*32 + jb);
            ulonglong2 c3 = *(const ulonglong2*)(corr13d + g*32 + jb);

            #pragma unroll
            for (int i = 0; i < 7; ++i) {
                ffma2(A0[i], E[i],   w0.x);  ffma2(A1[i], E[i],   w0.y);
                ffma2(A0[i], E[i+1], w2.x);  ffma2(A1[i], E[i+1], w2.y);
                ffma2(A0[i], E[i+2], w4.x);  ffma2(A1[i], E[i+2], w4.y);
            }
            #pragma unroll
            for (int i = 0; i < 8; ++i) {
                ffma2(B0[i], E[i],   w1.x);  ffma2(B1[i], E[i],   w1.y);
                ffma2(B0[i], E[i+1], w3.x);  ffma2(B1[i], E[i+1], w3.y);
            }
            ffma2(A0[0], E[1], c0.x);  ffma2(A1[0], E[1], c0.y);
            ffma2(A0[6], E[7], c3.x);  ffma2(A1[6], E[7], c3.y);
        }

        int h_o = h + 1; if (h_o == 14) h_o = 0;   // roll(+1, H)

        #pragma unroll
        for (int jj = 0; jj < 2; ++jj) {
            ull* A = jj ? A1 : A0;
            ull* B = jj ? B1 : B0;
            float o[14];
            #pragma unroll
            for (int i = 0; i < 7; ++i) {
                float al, ah, bl0, bh0, bl1, bh1;
                unpack2(A[i],   al,  ah);
                unpack2(B[i],   bl0, bh0);
                unpack2(B[i+1], bl1, bh1);
                o[2*i]   = al + bh0;
                o[2*i+1] = ah + bl1;
            }
            int ch = (jb + jj)*16 + p;
            float* ob = out + obase + (size_t)ch*196 + h_o*14;
            if ((h_o & 1) == 0) {               // 16B aligned
                *(float4*)(ob)      = make_float4(o[0], o[1], o[2], o[3]);
                *(float4*)(ob + 4)  = make_float4(o[4], o[5], o[6], o[7]);
                *(float4*)(ob + 8)  = make_float4(o[8], o[9], o[10], o[11]);
                *(float2*)(ob + 12) = make_float2(o[12], o[13]);
            } else {                            // 8B aligned
                *(float2*)(ob)      = make_float2(o[0], o[1]);
                *(float4*)(ob + 2)  = make_float4(o[2], o[3], o[4], o[5]);
                *(float4*)(ob + 6)  = make_float4(o[6], o[7], o[8], o[9]);
                *(float4*)(ob + 10) = make_float4(o[10], o[11], o[12], o[13]);
            }
        }
    }
}

extern "C" void kernel_launch(void* const* d_in, const int* in_sizes, int n_in,
                              void* d_out, int out_size) {
    const float* x     = (const float*)d_in[0];
    const float* wconv = (const float*)d_in[1];
    const float* wmix  = (const float*)d_in[2];
    float* out = (float*)d_out;
    (void)in_sizes; (void)n_in; (void)out_size;

    cudaFuncSetAttribute(fused_mix_unfold_conv,
                         cudaFuncAttributeMaxDynamicSharedMemorySize,
                         SMEM_BYTES);
    fused_mix_unfold_conv<<<128, 512, SMEM_BYTES>>>(x, wconv, wmix, out);
}